// round 14
// baseline (speedup 1.0000x reference)
#include <cuda_runtime.h>
#include <cuda_bf16.h>

// AdEx neuron sim, sm_103a. Round 12.
// Hypothesis: kernel is LSU/MIO-throughput bound (42 mem-ops/SM/step-round @
// ~4.5 cyc ≈ 190 cyc = observed step-round). Test: float2 (2 neurons/thread)
// halves mem-op count (LDG.64/STG.64): 10.6 warps x (4 + 7.75) ≈ 125 cyc.
// Step math is R11's verbatim per lane (speculative E, predicate refractory,
// dead-clip removed) — numerics unchanged (rel_err 2.3e-8).
// 128 thr/block x 391 blocks (same 2.64 CTA/SM as best scalar config).

#define UNROLL 16

#define C_EL        (-70.6e-3f)
#define C_VT        (-50.4e-3f)
#define C_GL        (30.0e-9f)
#define C_DTCM      (3.5587188612099645e6f)   // DT / CM
#define C_DTTAUW    (6.944444444444445e-3f)   // DT / TAUW
#define C_A         (4.0e-9f)
#define C_B         (0.0805e-9f)
// y = (v - VT)*500*log2e + log2(GL*DELTAT)  ==  fma(v, C_YSLOPE, C_YB2)
#define C_YSLOPE    (721.3475204444817f)      // 500 * log2(e)
#define C_YB2       (2.3996684904f)           // log2(6e-11) - VT*C_YSLOPE

// p1 = spiked last step, p2 = spiked two steps ago  (REF_STEPS = 2)
// E carries GL*DELTAT*exp((v - VT)/DELTAT) for the CURRENT v.
__device__ __forceinline__ void adex_step(float It, float E_EL,
                                          float& v, float& E, float& c,
                                          bool& p1, bool& p2, float& v_out) {
    bool in_ref = p1 | p2;

    float s23 = It - c;                 // off critical path
    float ve  = v - C_EL;

    float s1 = fmaf(-C_GL, ve, E);
    float s4 = s1 + s23;
    float v_new = fmaf(C_DTCM, s4, v);

    bool raw   = (v_new >= C_VT);
    bool sel   = raw | in_ref;
    bool spike = raw & (!in_ref);

    // speculative exp for next step (FSETP overlaps EX2)
    float y = fmaf(v_new, C_YSLOPE, C_YB2);
    float E_spec;
    asm("ex2.approx.ftz.f32 %0, %1;" : "=f"(E_spec) : "f"(y));

    float c_mid = fmaf(C_A, ve, -c);
    float c_new = fmaf(C_DTTAUW, c_mid, c);

    v = sel ? C_EL : v_new;
    E = sel ? E_EL : E_spec;
    c = spike ? (c_new + C_B) : c_new;
    p2 = p1;
    p1 = spike;
    v_out = v;
}

__device__ __forceinline__ float make_E(float v) {
    float y = fmaf(v, C_YSLOPE, C_YB2);
    float E;
    asm("ex2.approx.ftz.f32 %0, %1;" : "=f"(E) : "f"(y));
    return E;
}

// 2 neurons/thread, float2 I/O. N2 = N/2 (row stride in float2).
template<int N2_STATIC>
__global__ void __launch_bounds__(128) adex2_kernel(
    const float2* __restrict__ I,    // [T, N2]
    const float2* __restrict__ v0,
    const float2* __restrict__ c0,
    const int2*   __restrict__ ref0,
    float2*       __restrict__ out,  // [T, N2]
    int T, int N2_rt)
{
    const int N2 = (N2_STATIC > 0) ? N2_STATIC : N2_rt;
    int n = blockIdx.x * blockDim.x + threadIdx.x;
    if (n >= N2) return;

    float2 v2 = v0[n];
    float2 c2 = c0[n];
    int2   r2 = ref0[n];

    float va = v2.x, vb = v2.y;
    float ca = c2.x, cb = c2.y;
    bool p1a = (r2.x > 1), p2a = (r2.x == 1);
    bool p1b = (r2.y > 1), p2b = (r2.y == 1);
    if (p1a | p2a) va = C_EL;          // invariant: v==EL while refractory
    if (p1b | p2b) vb = C_EL;

    const float E_EL = make_E(C_EL);
    float Ea = make_E(va);
    float Eb = make_E(vb);

    const float2* Ip = I + n;
    float2*       Op = out + n;

    float2 buf[UNROLL];
    #pragma unroll
    for (int u = 0; u < UNROLL; ++u)
        buf[u] = (u < T) ? __ldcs(Ip + (size_t)u * N2) : make_float2(0.f, 0.f);

    int t = 0;
    for (; t + 2 * UNROLL <= T; t += UNROLL) {
        const float2* Ipn = Ip + (size_t)(t + UNROLL) * N2;  // +u*N2 -> immediates
        float2*       Opt = Op + (size_t)t * N2;
        #pragma unroll
        for (int u = 0; u < UNROLL; ++u) {
            float2 It = buf[u];
            buf[u] = __ldcs(Ipn + (size_t)u * N2);
            float2 ov;
            adex_step(It.x, E_EL, va, Ea, ca, p1a, p2a, ov.x);
            adex_step(It.y, E_EL, vb, Eb, cb, p1b, p2b, ov.y);
            __stcs(Opt + (size_t)u * N2, ov);
        }
    }

    // epilogue 1: consume resident rows, refill guarded
    #pragma unroll
    for (int u = 0; u < UNROLL; ++u) {
        int row = t + u;
        if (row < T) {
            float2 It = buf[u];
            int tt = row + UNROLL;
            float2 nx = (tt < T) ? __ldcs(Ip + (size_t)tt * N2) : make_float2(0.f, 0.f);
            float2 ov;
            adex_step(It.x, E_EL, va, Ea, ca, p1a, p2a, ov.x);
            adex_step(It.y, E_EL, vb, Eb, cb, p1b, p2b, ov.y);
            __stcs(Op + (size_t)row * N2, ov);
            buf[u] = nx;
        }
    }
    t += UNROLL;

    // epilogue 2: remaining < UNROLL rows
    #pragma unroll
    for (int u = 0; u < UNROLL; ++u) {
        int row = t + u;
        if (row < T) {
            float2 ov;
            adex_step(buf[u].x, E_EL, va, Ea, ca, p1a, p2a, ov.x);
            adex_step(buf[u].y, E_EL, vb, Eb, cb, p1b, p2b, ov.y);
            __stcs(Op + (size_t)row * N2, ov);
        }
    }
}

// scalar fallback (odd N / unexpected shapes)
__global__ void __launch_bounds__(256) adex_scalar_kernel(
    const float* __restrict__ I, const float* __restrict__ v0,
    const float* __restrict__ c0, const int* __restrict__ ref0,
    float* __restrict__ out, int T, int N)
{
    int n = blockIdx.x * blockDim.x + threadIdx.x;
    if (n >= N) return;
    float v = v0[n], c = c0[n];
    int ref = ref0[n];
    bool p1 = (ref > 1), p2 = (ref == 1);
    if (p1 | p2) v = C_EL;
    const float E_EL = make_E(C_EL);
    float E = make_E(v);
    for (int t = 0; t < T; ++t) {
        float ov;
        adex_step(I[(size_t)t * N + n], E_EL, v, E, c, p1, p2, ov);
        out[(size_t)t * N + n] = ov;
    }
}

extern "C" void kernel_launch(void* const* d_in, const int* in_sizes, int n_in,
                              void* d_out, int out_size)
{
    const float* I    = (const float*)d_in[0];
    const float* v0   = (const float*)d_in[1];
    const float* c0   = (const float*)d_in[2];
    const int*   ref0 = (const int*)  d_in[3];
    float*       out  = (float*)d_out;

    int N = in_sizes[1];
    int T = in_sizes[0] / N;

    if ((N & 1) == 0) {
        int N2 = N / 2;
        int threads = 128;
        int blocks  = (N2 + threads - 1) / threads;
        if (N2 == 50000) {
            adex2_kernel<50000><<<blocks, threads>>>(
                (const float2*)I, (const float2*)v0, (const float2*)c0,
                (const int2*)ref0, (float2*)out, T, N2);
        } else {
            adex2_kernel<0><<<blocks, threads>>>(
                (const float2*)I, (const float2*)v0, (const float2*)c0,
                (const int2*)ref0, (float2*)out, T, N2);
        }
    } else {
        int threads = 256;
        int blocks  = (N + threads - 1) / threads;
        adex_scalar_kernel<<<blocks, threads>>>(I, v0, c0, ref0, out, T, N);
    }
}

// round 15
// speedup vs baseline: 1.0343x; 1.0343x over previous
#include <cuda_runtime.h>
#include <cuda_bf16.h>

// AdEx neuron sim, sm_103a. Round 13.
// Scalar R11 shape (1 neuron/thread, 256/block, 391 blocks — warp count is the
// protected resource; K-neuron tilings proved losers in R9/R12).
// Recurrence cut 36 -> ~28 cyc: DTCM distributed so the non-exp update
//   w = v + DTCM*(It-c) - GL*DTCM*(v-EL)
// computes off-chain in parallel with EX2; chain is v_new -> y -> EX2 ->
// FSEL(E) -> fma(DTCM, E, w). Re-association delta ~3e-10 V/step, 6x below
// the proven flip-free perturbation level.

#define UNROLL 16

#define C_EL        (-70.6e-3f)
#define C_VT        (-50.4e-3f)
#define C_DTCM      (3.5587188612099645e6f)   // DT / CM
#define C_GLDTCM    (0.10676156583629893f)    // GL * DT / CM
#define C_DTTAUW    (6.944444444444445e-3f)   // DT / TAUW
#define C_A         (4.0e-9f)
#define C_B         (0.0805e-9f)
// y = (v - VT)*500*log2e + log2(GL*DELTAT)  ==  fma(v, C_YSLOPE, C_YB2)
#define C_YSLOPE    (721.3475204444817f)      // 500 * log2(e)
#define C_YB2       (2.3996684904f)           // log2(6e-11) - VT*C_YSLOPE

// p1 = spiked last step, p2 = spiked two steps ago  (REF_STEPS = 2)
// E carries GL*DELTAT*exp((v - VT)/DELTAT) for the CURRENT v.
__device__ __forceinline__ void adex_step(float It, float E_EL,
                                          float& v, float& E, float& c,
                                          bool& p1, bool& p2, float& v_out) {
    bool in_ref = p1 | p2;

    // off the E-chain: w from (v, c, It), overlaps EX2 of previous step
    float s23 = It - c;
    float ve  = v - C_EL;
    float w0  = fmaf(C_DTCM, s23, v);
    float w   = fmaf(-C_GLDTCM, ve, w0);

    // critical chain: E -> v_new -> y -> EX2 -> select
    float v_new = fmaf(C_DTCM, E, w);

    bool raw   = (v_new >= C_VT);
    bool sel   = raw | in_ref;
    bool spike = raw & (!in_ref);

    // speculative exp for next step (FSETP overlaps EX2)
    float y = fmaf(v_new, C_YSLOPE, C_YB2);
    float E_spec;
    asm("ex2.approx.ftz.f32 %0, %1;" : "=f"(E_spec) : "f"(y));

    float c_mid = fmaf(C_A, ve, -c);
    float c_new = fmaf(C_DTTAUW, c_mid, c);

    v = sel ? C_EL : v_new;
    E = sel ? E_EL : E_spec;
    c = spike ? (c_new + C_B) : c_new;
    p2 = p1;
    p1 = spike;
    v_out = v;
}

__device__ __forceinline__ float make_E(float v) {
    float y = fmaf(v, C_YSLOPE, C_YB2);
    float E;
    asm("ex2.approx.ftz.f32 %0, %1;" : "=f"(E) : "f"(y));
    return E;
}

template<int N_STATIC>
__global__ void __launch_bounds__(256) adex_kernel(
    const float* __restrict__ I,    // [T, N]
    const float* __restrict__ v0,
    const float* __restrict__ c0,
    const int*   __restrict__ ref0,
    float*       __restrict__ out,  // [T, N]
    int T, int N_rt)
{
    const int N = (N_STATIC > 0) ? N_STATIC : N_rt;
    int n = blockIdx.x * blockDim.x + threadIdx.x;
    if (n >= N) return;

    float v   = v0[n];
    float c   = c0[n];
    int   ref = ref0[n];
    bool  p1  = (ref > 1);        // spiked last step
    bool  p2  = (ref == 1);       // spiked two steps ago
    if (p1 | p2) v = C_EL;        // invariant: v==EL while refractory

    const float E_EL = make_E(C_EL);
    float E = make_E(v);

    const float* Ip = I + n;
    float*       Op = out + n;

    float buf[UNROLL];
    #pragma unroll
    for (int u = 0; u < UNROLL; ++u)
        buf[u] = (u < T) ? __ldcs(Ip + (size_t)u * N) : 0.0f;

    int t = 0;
    for (; t + 2 * UNROLL <= T; t += UNROLL) {
        const float* Ipn = Ip + (size_t)(t + UNROLL) * N;  // +u*N fold to immediates
        float*       Opt = Op + (size_t)t * N;
        #pragma unroll
        for (int u = 0; u < UNROLL; ++u) {
            float It = buf[u];
            buf[u] = __ldcs(Ipn + (size_t)u * N);
            float ov;
            adex_step(It, E_EL, v, E, c, p1, p2, ov);
            __stcs(Opt + (size_t)u * N, ov);
        }
    }

    // epilogue 1: consume resident rows, refill guarded
    #pragma unroll
    for (int u = 0; u < UNROLL; ++u) {
        int row = t + u;
        if (row < T) {
            float It = buf[u];
            int tt = row + UNROLL;
            float nx = (tt < T) ? __ldcs(Ip + (size_t)tt * N) : 0.0f;
            float ov;
            adex_step(It, E_EL, v, E, c, p1, p2, ov);
            __stcs(Op + (size_t)row * N, ov);
            buf[u] = nx;
        }
    }
    t += UNROLL;

    // epilogue 2: remaining < UNROLL rows
    #pragma unroll
    for (int u = 0; u < UNROLL; ++u) {
        int row = t + u;
        if (row < T) {
            float ov;
            adex_step(buf[u], E_EL, v, E, c, p1, p2, ov);
            __stcs(Op + (size_t)row * N, ov);
        }
    }
}

extern "C" void kernel_launch(void* const* d_in, const int* in_sizes, int n_in,
                              void* d_out, int out_size)
{
    const float* I    = (const float*)d_in[0];
    const float* v0   = (const float*)d_in[1];
    const float* c0   = (const float*)d_in[2];
    const int*   ref0 = (const int*)  d_in[3];
    float*       out  = (float*)d_out;

    int N = in_sizes[1];
    int T = in_sizes[0] / N;

    int threads = 256;
    int blocks  = (N + threads - 1) / threads;

    if (N == 100000) {
        adex_kernel<100000><<<blocks, threads>>>(I, v0, c0, ref0, out, T, N);
    } else {
        adex_kernel<0><<<blocks, threads>>>(I, v0, c0, ref0, out, T, N);
    }
}

// round 16
// speedup vs baseline: 1.0545x; 1.0195x over previous
#include <cuda_runtime.h>
#include <cuda_bf16.h>

// AdEx neuron sim, sm_103a. Round 14.
// Numerics: R11 step restored verbatim (s1/s4 ordering, speculative E,
// predicate refractory) — proven rel_err 2.3e-8. R13's DTCM-distribution
// reverted (no wall gain, 85x error-budget cost).
// New: phase-batched memory ops. Each UNROLL=16 group runs
//   [16 LDG burst] -> [16 compute steps, outputs in regs] -> [16 STG burst]
// to give the HBM controller long same-direction runs (50/50 R/W mix currently
// caps us at ~65% of peak; fine-grained interleave suspected cause).

#define UNROLL 16

#define C_EL        (-70.6e-3f)
#define C_VT        (-50.4e-3f)
#define C_GL        (30.0e-9f)
#define C_DTCM      (3.5587188612099645e6f)   // DT / CM
#define C_DTTAUW    (6.944444444444445e-3f)   // DT / TAUW
#define C_A         (4.0e-9f)
#define C_B         (0.0805e-9f)
// y = (v - VT)*500*log2e + log2(GL*DELTAT)  ==  fma(v, C_YSLOPE, C_YB2)
#define C_YSLOPE    (721.3475204444817f)      // 500 * log2(e)
#define C_YB2       (2.3996684904f)           // log2(6e-11) - VT*C_YSLOPE

// p1 = spiked last step, p2 = spiked two steps ago  (REF_STEPS = 2)
// E carries GL*DELTAT*exp((v - VT)/DELTAT) for the CURRENT v.  (R11 verbatim)
__device__ __forceinline__ void adex_step(float It, float E_EL,
                                          float& v, float& E, float& c,
                                          bool& p1, bool& p2, float& v_out) {
    bool in_ref = p1 | p2;

    float s23 = It - c;                 // off critical path
    float ve  = v - C_EL;

    float s1 = fmaf(-C_GL, ve, E);
    float s4 = s1 + s23;
    float v_new = fmaf(C_DTCM, s4, v);

    bool raw   = (v_new >= C_VT);
    bool sel   = raw | in_ref;
    bool spike = raw & (!in_ref);

    // speculative exp for next step (FSETP overlaps EX2)
    float y = fmaf(v_new, C_YSLOPE, C_YB2);
    float E_spec;
    asm("ex2.approx.ftz.f32 %0, %1;" : "=f"(E_spec) : "f"(y));

    float c_mid = fmaf(C_A, ve, -c);
    float c_new = fmaf(C_DTTAUW, c_mid, c);

    v = sel ? C_EL : v_new;
    E = sel ? E_EL : E_spec;
    c = spike ? (c_new + C_B) : c_new;
    p2 = p1;
    p1 = spike;
    v_out = v;
}

__device__ __forceinline__ float make_E(float v) {
    float y = fmaf(v, C_YSLOPE, C_YB2);
    float E;
    asm("ex2.approx.ftz.f32 %0, %1;" : "=f"(E) : "f"(y));
    return E;
}

template<int N_STATIC>
__global__ void __launch_bounds__(256) adex_kernel(
    const float* __restrict__ I,    // [T, N]
    const float* __restrict__ v0,
    const float* __restrict__ c0,
    const int*   __restrict__ ref0,
    float*       __restrict__ out,  // [T, N]
    int T, int N_rt)
{
    const int N = (N_STATIC > 0) ? N_STATIC : N_rt;
    int n = blockIdx.x * blockDim.x + threadIdx.x;
    if (n >= N) return;

    float v   = v0[n];
    float c   = c0[n];
    int   ref = ref0[n];
    bool  p1  = (ref > 1);        // spiked last step
    bool  p2  = (ref == 1);       // spiked two steps ago
    if (p1 | p2) v = C_EL;        // invariant: v==EL while refractory

    const float E_EL = make_E(C_EL);
    float E = make_E(v);

    const float* Ip = I + n;
    float*       Op = out + n;

    // prime rows 0..UNROLL-1
    float buf[UNROLL];
    #pragma unroll
    for (int u = 0; u < UNROLL; ++u)
        buf[u] = (u < T) ? __ldcs(Ip + (size_t)u * N) : 0.0f;

    int t = 0;
    for (; t + 2 * UNROLL <= T; t += UNROLL) {
        const float* Ipn = Ip + (size_t)(t + UNROLL) * N;  // +u*N fold to immediates
        float*       Opt = Op + (size_t)t * N;

        // phase 1: burst-load next group's rows
        float nbuf[UNROLL];
        #pragma unroll
        for (int u = 0; u < UNROLL; ++u)
            nbuf[u] = __ldcs(Ipn + (size_t)u * N);

        // phase 2: compute all steps, outputs held in registers
        float ov[UNROLL];
        #pragma unroll
        for (int u = 0; u < UNROLL; ++u)
            adex_step(buf[u], E_EL, v, E, c, p1, p2, ov[u]);

        // phase 3: burst-store the group's outputs
        #pragma unroll
        for (int u = 0; u < UNROLL; ++u)
            __stcs(Opt + (size_t)u * N, ov[u]);

        #pragma unroll
        for (int u = 0; u < UNROLL; ++u) buf[u] = nbuf[u];
    }

    // epilogue 1: consume resident rows, refill guarded
    #pragma unroll
    for (int u = 0; u < UNROLL; ++u) {
        int row = t + u;
        if (row < T) {
            float It = buf[u];
            int tt = row + UNROLL;
            float nx = (tt < T) ? __ldcs(Ip + (size_t)tt * N) : 0.0f;
            float ov1;
            adex_step(It, E_EL, v, E, c, p1, p2, ov1);
            __stcs(Op + (size_t)row * N, ov1);
            buf[u] = nx;
        }
    }
    t += UNROLL;

    // epilogue 2: remaining < UNROLL rows
    #pragma unroll
    for (int u = 0; u < UNROLL; ++u) {
        int row = t + u;
        if (row < T) {
            float ov1;
            adex_step(buf[u], E_EL, v, E, c, p1, p2, ov1);
            __stcs(Op + (size_t)row * N, ov1);
        }
    }
}

extern "C" void kernel_launch(void* const* d_in, const int* in_sizes, int n_in,
                              void* d_out, int out_size)
{
    const float* I    = (const float*)d_in[0];
    const float* v0   = (const float*)d_in[1];
    const float* c0   = (const float*)d_in[2];
    const int*   ref0 = (const int*)  d_in[3];
    float*       out  = (float*)d_out;

    int N = in_sizes[1];
    int T = in_sizes[0] / N;

    int threads = 256;
    int blocks  = (N + threads - 1) / threads;

    if (N == 100000) {
        adex_kernel<100000><<<blocks, threads>>>(I, v0, c0, ref0, out, T, N);
    } else {
        adex_kernel<0><<<blocks, threads>>>(I, v0, c0, ref0, out, T, N);
    }
}